// round 11
// baseline (speedup 1.0000x reference)
#include <cuda_runtime.h>
#include <cuda_bf16.h>
#include <cstdint>

// Problem constants: T=64, B=512, H=512.
#define T_DIM 64
#define B_DIM 512
#define H4    128                     // float4 per full row
#define ROW_F4 64                     // float4 per HALF row
#define ROW_BYTES 1024                // bytes per half row
#define SLOTS 65                      // slot 0 = init, 1..64 = distinct sources
#define SMEM_BYTES (SLOTS * ROW_BYTES)

// One block per (lane b, half of H). Phase 1: parallel scan ->
//   src[t] = -1 if P[t]==0 else max{ u<=t : P[u-1]==P[t]-1 },  P = prefix(ops)
// then rank distinct sources. Phase A: TMA bulk-load distinct half-rows into
// SMEM (engine does the reads). Phase B: 64 TMA bulk-stores SMEM->gmem
// (stores never touch L1tex or the register file).
__global__ void __launch_bounds__(128, 3) fused_kernel(
    const float4* __restrict__ inputs,   // (T,B,H) as float4
    const float4* __restrict__ init_h,   // (H,)    as float4
    const int*    __restrict__ ops,      // (T,B)
    float4*       __restrict__ out)      // (T,B,H) as float4
{
    extern __shared__ __align__(16) unsigned char stage[];   // SLOTS * 1KB
    __shared__ int s_P[T_DIM + 1];           // s_P[u] = P[u-1], s_P[0]=0
    __shared__ int s_src[T_DIM];
    __shared__ int s_pres[T_DIM];
    __shared__ int s_rank[T_DIM];
    __shared__ int s_slotsrc[SLOTS];
    __shared__ int s_slot[T_DIM];
    __shared__ int s_w0, s_w0b, s_n;
    __shared__ __align__(8) unsigned long long s_mbar;

    const int bid  = blockIdx.x;
    const int b    = bid >> 1;
    const int half = bid & 1;
    const int tid  = threadIdx.x;
    const unsigned mask = 0xFFFFFFFFu;
    const unsigned mb   = (unsigned)__cvta_generic_to_shared(&s_mbar);
    const unsigned st0  = (unsigned)__cvta_generic_to_shared(stage);

    if (tid == 0)
        asm volatile("mbarrier.init.shared.b64 [%0], 1;" :: "r"(mb) : "memory");

    // ---- Phase 1a: two-warp inclusive scan of ops column b ----
    int p = 0;
    if (tid < T_DIM) {
        s_pres[tid] = 0;
        p = ops[tid * B_DIM + b];
        #pragma unroll
        for (int d = 1; d < 32; d <<= 1) {
            int n = __shfl_up_sync(mask, p, d);
            if ((tid & 31) >= d) p += n;
        }
        if (tid == 31) s_w0 = p;
        if (tid == 0)  s_P[0] = 0;
    }
    __syncthreads();
    if (tid >= 32 && tid < T_DIM) p += s_w0;
    if (tid < T_DIM) s_P[tid + 1] = p;
    __syncthreads();

    // ---- Phase 1b: per-t backward search for the matching writer ----
    if (tid < T_DIM) {
        int Pt  = s_P[tid + 1];
        int src = -1;
        if (Pt > 0) {
            int target = Pt - 1;
            #pragma unroll 1
            for (int u = tid; u >= 0; --u) {
                if (s_P[u] == target) { src = u; break; }
            }
        }
        s_src[tid] = src;
        if (src >= 0) s_pres[src] = 1;       // benign races
    }
    __syncthreads();

    // ---- Phase 1c: rank distinct sources (second 2-warp scan) ----
    int r = 0;
    if (tid < T_DIM) {
        r = s_pres[tid];
        #pragma unroll
        for (int d = 1; d < 32; d <<= 1) {
            int n = __shfl_up_sync(mask, r, d);
            if ((tid & 31) >= d) r += n;
        }
        if (tid == 31) s_w0b = r;
    }
    __syncthreads();
    if (tid >= 32 && tid < T_DIM) r += s_w0b;
    if (tid < T_DIM) {
        s_rank[tid] = r;                     // inclusive rank: source -> slot r
        if (s_pres[tid]) s_slotsrc[r] = tid; // r in [1,64], SLOTS=65 always fits
        if (tid == T_DIM - 1) s_n = r;       // number of distinct sources
    }
    __syncthreads();
    if (tid < T_DIM) {
        int s = s_src[tid];
        s_slot[tid] = (s < 0) ? 0 : s_rank[s];
    }
    __syncthreads();

    // ---- Phase A: TMA bulk-load init row + distinct rows into SMEM ----
    if (tid == 0) {
        int ntx = (s_n + 1) * ROW_BYTES;
        asm volatile("mbarrier.arrive.expect_tx.shared.b64 _, [%0], %1;"
                     :: "r"(mb), "r"(ntx) : "memory");
        const float4* g0 = init_h + half * ROW_F4;
        asm volatile(
            "cp.async.bulk.shared::cluster.global.mbarrier::complete_tx::bytes "
            "[%0], [%1], %2, [%3];"
            :: "r"(st0), "l"(g0), "r"(ROW_BYTES), "r"(mb) : "memory");
        int nd = s_n;
        #pragma unroll 1
        for (int k = 1; k <= nd; ++k) {
            const float4* g = inputs
                + ((unsigned)(s_slotsrc[k] * B_DIM + b)) * H4 + half * ROW_F4;
            asm volatile(
                "cp.async.bulk.shared::cluster.global.mbarrier::complete_tx::bytes "
                "[%0], [%1], %2, [%3];"
                :: "r"(st0 + (unsigned)k * ROW_BYTES), "l"(g), "r"(ROW_BYTES),
                   "r"(mb) : "memory");
        }
    }
    // all threads wait for all staged bytes
    {
        asm volatile(
            "{\n\t.reg .pred P;\n"
            "WAIT_%=:\n\t"
            "mbarrier.try_wait.parity.shared::cta.b64 P, [%0], 0;\n\t"
            "@!P bra WAIT_%=;\n\t}"
            :: "r"(mb) : "memory");
    }

    // ---- Phase B: 64 TMA bulk-stores SMEM -> gmem ----
    if (tid < T_DIM) {
        float4* dst = out + ((unsigned)(tid * B_DIM + b)) * H4 + half * ROW_F4;
        unsigned srcs = st0 + (unsigned)s_slot[tid] * ROW_BYTES;
        asm volatile("cp.async.bulk.global.shared::cta.bulk_group [%0], [%1], %2;"
                     :: "l"(dst), "r"(srcs), "r"(ROW_BYTES) : "memory");
        asm volatile("cp.async.bulk.commit_group;" ::: "memory");
        asm volatile("cp.async.bulk.wait_group 0;" ::: "memory");
    }
}

extern "C" void kernel_launch(void* const* d_in, const int* in_sizes, int n_in,
                              void* d_out, int out_size) {
    const float* inputs = (const float*)d_in[0];   // (T,B,H) f32
    const float* init_h = (const float*)d_in[1];   // (H,)    f32
    const int*   ops    = (const int*)d_in[2];     // (T,B)   i32
    float* out = (float*)d_out;                    // (T,B,H) f32

    cudaFuncSetAttribute(fused_kernel,
                         cudaFuncAttributeMaxDynamicSharedMemorySize, SMEM_BYTES);

    fused_kernel<<<2 * B_DIM, 128, SMEM_BYTES>>>(
        (const float4*)inputs, (const float4*)init_h, ops, (float4*)out);
}

// round 13
// speedup vs baseline: 1.1792x; 1.1792x over previous
#include <cuda_runtime.h>
#include <cuda_bf16.h>

// Problem constants: T=64, B=512, H=512.
#define T_DIM 64
#define B_DIM 512
#define H4    128                    // float4 per full row
#define ROW_F4 64                    // float4 per HALF row
#define STRIDE (B_DIM * H4)          // float4 stride between consecutive t
#define CHUNK_T 16                   // rows per chunk
#define NCHUNK  (T_DIM / CHUNK_T)    // 4

// Grid: 1024 blocks x 256 threads, block = (lane b, half of H).
// Phase 1 (parallel scan, proven): src[t] = -1 if P[t]==0 else
//   max{ u<=t : P[u-1]==P[t]-1 },  P = prefix(ops).
// Phase 2: LDG gather -> SMEM staging -> cp.async.bulk 1KB stores (async
// proxy path; stores bypass L1tex/STG entirely). Double-buffered chunks.
__global__ void __launch_bounds__(256) fused_kernel(
    const float4* __restrict__ inputs,   // (T,B,H) as float4
    const float4* __restrict__ init_h,   // (H,)    as float4
    const int*    __restrict__ ops,      // (T,B)
    float4*       __restrict__ out)      // (T,B,H) as float4
{
    __shared__ float4 buf[2][CHUNK_T][ROW_F4];   // 2 x 16KB staging
    __shared__ int s_P[T_DIM + 1];               // s_P[u] = P[u-1]
    __shared__ int s_src[T_DIM];
    __shared__ int s_w0;

    const int bid  = blockIdx.x;
    const int b    = bid >> 1;
    const int half = bid & 1;
    const int tid  = threadIdx.x;

    // ---- Phase 1a: two-warp inclusive scan of ops column b ----
    int p = 0;
    if (tid < T_DIM) {
        p = ops[tid * B_DIM + b];
        #pragma unroll
        for (int d = 1; d < 32; d <<= 1) {
            int n = __shfl_up_sync(0xFFFFFFFFu, p, d);
            if ((tid & 31) >= d) p += n;
        }
        if (tid == 31) s_w0 = p;
        if (tid == 0)  s_P[0] = 0;
    }
    __syncthreads();
    if (tid >= 32 && tid < T_DIM) p += s_w0;
    if (tid < T_DIM) s_P[tid + 1] = p;
    __syncthreads();

    // ---- Phase 1b: per-t backward search for the matching writer ----
    if (tid < T_DIM) {
        int Pt  = s_P[tid + 1];
        int src = -1;
        if (Pt > 0) {
            int target = Pt - 1;
            #pragma unroll 1
            for (int u = tid; u >= 0; --u) {
                if (s_P[u] == target) { src = u; break; }
            }
        }
        s_src[tid] = src;
    }
    __syncthreads();

    // ---- Phase 2: chunked gather -> SMEM -> bulk-store pipeline ----
    const int col = tid & (ROW_F4 - 1);          // 0..63 (f4 column in half)
    const int tr  = tid >> 6;                    // 0..3
    const int h4  = half * ROW_F4 + col;
    const float4* __restrict__ in_base  = inputs + (unsigned)b * H4 + h4;
    const float4  vinit = init_h[h4];

    #pragma unroll 1
    for (int c = 0; c < NCHUNK; ++c) {
        const int pb = c & 1;
        // buffer pb was handed to the bulk-store engine in chunk c-2;
        // allow 1 outstanding group, then make sure issuers are done.
        if (c >= 2) {
            if (tid < CHUNK_T)
                asm volatile("cp.async.bulk.wait_group 1;" ::: "memory");
            __syncthreads();
        }
        // gather 4 rows per thread into staging (loads batched -> MLP=4)
        int   s[4];
        float4 v[4];
        #pragma unroll
        for (int j = 0; j < 4; ++j)
            s[j] = s_src[c * CHUNK_T + tr + 4 * j];
        #pragma unroll
        for (int j = 0; j < 4; ++j) {
            v[j] = vinit;
            if (s[j] >= 0) v[j] = __ldg(in_base + (unsigned)s[j] * STRIDE);
        }
        #pragma unroll
        for (int j = 0; j < 4; ++j)
            buf[pb][tr + 4 * j][col] = v[j];

        __syncthreads();
        asm volatile("fence.proxy.async.shared::cta;" ::: "memory");
        // 16 threads each issue one 1KB bulk store (async proxy path)
        if (tid < CHUNK_T) {
            int t = c * CHUNK_T + tid;
            float4* dst = out + ((unsigned)(t * B_DIM + b)) * H4 + half * ROW_F4;
            unsigned ss = (unsigned)__cvta_generic_to_shared(&buf[pb][tid][0]);
            asm volatile(
                "cp.async.bulk.global.shared::cta.bulk_group [%0], [%1], %2;"
                :: "l"(dst), "r"(ss), "n"(ROW_F4 * 16) : "memory");
            asm volatile("cp.async.bulk.commit_group;" ::: "memory");
        }
    }
    // drain all outstanding bulk stores before CTA exit
    if (tid < CHUNK_T)
        asm volatile("cp.async.bulk.wait_group 0;" ::: "memory");
}

extern "C" void kernel_launch(void* const* d_in, const int* in_sizes, int n_in,
                              void* d_out, int out_size) {
    const float* inputs = (const float*)d_in[0];   // (T,B,H) f32
    const float* init_h = (const float*)d_in[1];   // (H,)    f32
    const int*   ops    = (const int*)d_in[2];     // (T,B)   i32
    float* out = (float*)d_out;                    // (T,B,H) f32

    fused_kernel<<<2 * B_DIM, 256>>>(
        (const float4*)inputs, (const float4*)init_h, ops, (float4*)out);
}